// round 3
// baseline (speedup 1.0000x reference)
#include <cuda_runtime.h>
#include <cstdint>

// ---------------------------------------------------------------------------
// Problem constants
//   B=4, T=1024, DIM=1024, HEADS=16, DH=64, MEM=1024, CMEM=256, KV=2304,
//   TOTAL_MEM=1280, scale = 1/8.
// Outputs concatenated: logits (4M) | new_mem (4M) | new_cmem (1M) floats.
//   new_mem  == x  (queue[:, -MEM:] with queue = [mem; x])
//   new_cmem == conv(mem) (cmem rows fall off the CMEM window)
// ---------------------------------------------------------------------------

// Scratch (static device arrays; allocation-free rule)
__device__ float g_q [4u * 1024u * 1024u];          // (B,T,DIM)       16 MB
__device__ float g_kv[4u * 2304u * 2048u];          // (B,KV,2*DIM)  75.5 MB
__device__ float g_ao[4u * 1024u * 1024u];          // attn out       16 MB
__device__ float g_wt[4096u * 1024u];               // conv_w^T [k][o] 16 MB

// ---------------------------------------------------------------------------
// Tiled SGEMM: C[M,N] = A[M,K] * B[N,K]^T (+bias). 128x128 tile, BK=16,
// 256 threads, 8x8 per-thread micro-tile.
// MODE 0: q = x @ Wq^T                    -> g_q
// MODE 1: kv = gather(cmem,mem,x) @ Wkv^T -> g_kv
// MODE 2: logits = g_ao @ Wout^T + bout   -> d_out
// MODE 3: conv: A rows = mem (contig K=4096), B = g_wt [k][n], +conv_b
// ---------------------------------------------------------------------------
template<int MODE>
__global__ __launch_bounds__(256)
void gemm_tpl(const float* __restrict__ A0, const float* __restrict__ A1,
              const float* __restrict__ A2, const float* __restrict__ Bw,
              const float* __restrict__ bias, float* __restrict__ Cparam,
              int K, int ldc)
{
    __shared__ float At[16][132];   // At[k][m]
    __shared__ float Bt[16][132];   // Bt[k][n]

    const int tid = threadIdx.x;
    const int m0 = blockIdx.y * 128;
    const int n0 = blockIdx.x * 128;
    const int tr = (tid >> 4) << 3;
    const int tc = (tid & 15) << 3;

    float* Cp;
    if (MODE == 0)      Cp = g_q;
    else if (MODE == 1) Cp = g_kv;
    else                Cp = Cparam;

    // A row base pointers for the 2 rows this thread loads per k-step
    const float* arowp[2];
#pragma unroll
    for (int i = 0; i < 2; ++i) {
        int f = tid + i * 256;
        int mrow = f >> 2;
        int mg = m0 + mrow;
        if (MODE == 1) {
            int b = mg / 2304;
            int s = mg - b * 2304;
            if (s < 256)       arowp[i] = A2 + ((size_t)b * 256  + s)          * 1024; // cmem
            else if (s < 1280) arowp[i] = A1 + ((size_t)b * 1024 + (s - 256))  * 1024; // mem
            else               arowp[i] = A0 + ((size_t)b * 1024 + (s - 1280)) * 1024; // x
        } else if (MODE == 3) {
            int b = mg >> 8;
            int t4 = (mg & 255) << 2;   // 4*t'
            arowp[i] = A1 + ((size_t)b * 1024 + t4) * 1024;  // mem rows, K=4096 contiguous
        } else if (MODE == 2) {
            arowp[i] = g_ao + (size_t)mg * 1024;
        } else {
            arowp[i] = A0 + (size_t)mg * 1024;
        }
    }

    float acc[8][8];
#pragma unroll
    for (int a = 0; a < 8; ++a)
#pragma unroll
        for (int b = 0; b < 8; ++b) acc[a][b] = 0.f;

    for (int k0 = 0; k0 < K; k0 += 16) {
#pragma unroll
        for (int i = 0; i < 2; ++i) {
            int f = tid + i * 256;
            int mrow = f >> 2;
            int kq = (f & 3) << 2;
            float4 av = *(const float4*)(arowp[i] + k0 + kq);
            At[kq + 0][mrow] = av.x; At[kq + 1][mrow] = av.y;
            At[kq + 2][mrow] = av.z; At[kq + 3][mrow] = av.w;
            if (MODE == 3) {
                int kr = f >> 5;             // 0..15
                int n4 = (f & 31) << 2;      // 0..124
                float4 bv = *(const float4*)&g_wt[(size_t)(k0 + kr) * 1024 + n0 + n4];
                *(float4*)&Bt[kr][n4] = bv;
            } else {
                float4 bv = *(const float4*)(Bw + (size_t)(n0 + mrow) * K + k0 + kq);
                Bt[kq + 0][mrow] = bv.x; Bt[kq + 1][mrow] = bv.y;
                Bt[kq + 2][mrow] = bv.z; Bt[kq + 3][mrow] = bv.w;
            }
        }
        __syncthreads();
#pragma unroll
        for (int kk = 0; kk < 16; ++kk) {
            float af[8], bf[8];
            *(float4*)(af)     = *(const float4*)&At[kk][tr];
            *(float4*)(af + 4) = *(const float4*)&At[kk][tr + 4];
            *(float4*)(bf)     = *(const float4*)&Bt[kk][tc];
            *(float4*)(bf + 4) = *(const float4*)&Bt[kk][tc + 4];
#pragma unroll
            for (int a = 0; a < 8; ++a)
#pragma unroll
                for (int b = 0; b < 8; ++b)
                    acc[a][b] = fmaf(af[a], bf[b], acc[a][b]);
        }
        __syncthreads();
    }

    float bb[8];
#pragma unroll
    for (int b = 0; b < 8; ++b) bb[b] = 0.f;
    if (MODE >= 2) {
        *(float4*)(bb)     = *(const float4*)&bias[n0 + tc];
        *(float4*)(bb + 4) = *(const float4*)&bias[n0 + tc + 4];
    }
#pragma unroll
    for (int a = 0; a < 8; ++a) {
        float* crow = Cp + (size_t)(m0 + tr + a) * ldc + n0 + tc;
        float4 v0, v1;
        v0.x = acc[a][0] + bb[0]; v0.y = acc[a][1] + bb[1];
        v0.z = acc[a][2] + bb[2]; v0.w = acc[a][3] + bb[3];
        v1.x = acc[a][4] + bb[4]; v1.y = acc[a][5] + bb[5];
        v1.z = acc[a][6] + bb[6]; v1.w = acc[a][7] + bb[7];
        *(float4*)(crow)     = v0;
        *(float4*)(crow + 4) = v1;
    }
}

// ---------------------------------------------------------------------------
// conv_w transpose: g_wt[r*1024 + i][o] = conv_w[o][i][r]
// ---------------------------------------------------------------------------
__global__ __launch_bounds__(256)
void transpose_w(const float* __restrict__ w)
{
    int k = blockIdx.y;                 // 0..4095 (= r*1024 + i)
    int i = k & 1023;
    int rr = k >> 10;
    int o = blockIdx.x * 256 + threadIdx.x;
    g_wt[(size_t)k * 1024 + o] = w[(size_t)o * 4096 + i * 4 + rr];
}

// ---------------------------------------------------------------------------
// Flash attention with Transformer-XL rel-pos shift.
// Block = (q-tile 64, head, batch). 256 threads; 4x4 micro-tiles.
//   S[qi,kj] = scale * ( q·k  +  q·pe[k0+kj + 1023 - (q0+qi)] )
// PE band per k-tile: rows c_base + p, p in [0,127), c_base = k0 + 960 - q0.
// Within the tile the pe row is p = 63 + kj - qi.
// Causal: valid iff kg <= qg + 1280; kend = q0 + 1344 (always <= 2304).
// ---------------------------------------------------------------------------
__global__ __launch_bounds__(256)
void attn_kernel(const float* __restrict__ pos_emb)
{
    extern __shared__ float sm[];
    float* Qt = sm;                 // [64][68] Qt[d][qi]
    float* Kt = sm + 64 * 68;       // [64][68] Kt[d][kj]
    float* Vs = sm + 2 * 64 * 68;   // [64][68] Vs[kj][d]
    float* Pt = sm + 3 * 64 * 68;   // [64][68] Pt[kj][qi]
    float* PE = sm + 4 * 64 * 68;   // [64][128] PE[d][p]

    const int tid = threadIdx.x;
    const int qt = blockIdx.x, h = blockIdx.y, bz = blockIdx.z;
    const int q0 = qt * 64;
    const int r = (tid >> 4) << 2;      // query row group 0..60
    const int c = (tid & 15) << 2;      // key col group 0..60
    const int pbase = 60 + c - r;       // in [0,120], mult of 4

    // Load Q tile (transposed)
    for (int idx = tid; idx < 1024; idx += 256) {
        int qi = idx >> 4, d4 = (idx & 15) << 2;
        float4 v = *(const float4*)&g_q[((size_t)(bz * 1024 + q0 + qi)) * 1024 + h * 64 + d4];
        Qt[(d4 + 0) * 68 + qi] = v.x; Qt[(d4 + 1) * 68 + qi] = v.y;
        Qt[(d4 + 2) * 68 + qi] = v.z; Qt[(d4 + 3) * 68 + qi] = v.w;
    }

    float O[4][4];
    float mrun[4], lrun[4];
#pragma unroll
    for (int a = 0; a < 4; ++a) {
        mrun[a] = -1e30f; lrun[a] = 0.f;
#pragma unroll
        for (int b = 0; b < 4; ++b) O[a][b] = 0.f;
    }

    const int kend = q0 + 1344;   // <= 2304 for all q0 <= 960

    for (int k0 = 0; k0 < kend; k0 += 64) {
        __syncthreads();   // prior-iteration readers done before overwriting tiles

        for (int idx = tid; idx < 1024; idx += 256) {
            int kj = idx >> 4, d4 = (idx & 15) << 2;
            size_t base = ((size_t)(bz * 2304 + k0 + kj)) * 2048 + h * 64;
            float4 kv4 = *(const float4*)&g_kv[base + d4];
            Kt[(d4 + 0) * 68 + kj] = kv4.x; Kt[(d4 + 1) * 68 + kj] = kv4.y;
            Kt[(d4 + 2) * 68 + kj] = kv4.z; Kt[(d4 + 3) * 68 + kj] = kv4.w;
            float4 vv = *(const float4*)&g_kv[base + 1024 + d4];
            *(float4*)&Vs[kj * 68 + d4] = vv;
        }
        int c_base = k0 + 960 - q0;   // >= 0 always
        for (int idx = tid; idx < 2048; idx += 256) {
            int p = idx >> 4, d4 = (idx & 15) << 2;
            int crow = c_base + p;
            float4 v = make_float4(0.f, 0.f, 0.f, 0.f);
            if (p < 127 && crow < 2304)
                v = *(const float4*)&pos_emb[((size_t)h * 2304 + crow) * 64 + d4];
            PE[(d4 + 0) * 128 + p] = v.x; PE[(d4 + 1) * 128 + p] = v.y;
            PE[(d4 + 2) * 128 + p] = v.z; PE[(d4 + 3) * 128 + p] = v.w;
        }
        __syncthreads();

        // --- S = Q·K^T + Q·PE(shifted) ---
        float s[4][4];
#pragma unroll
        for (int a = 0; a < 4; ++a)
#pragma unroll
            for (int b = 0; b < 4; ++b) s[a][b] = 0.f;

#pragma unroll 16
        for (int d = 0; d < 64; ++d) {
            float4 qv  = *(const float4*)&Qt[d * 68 + r];
            float4 kv4 = *(const float4*)&Kt[d * 68 + c];
            float4 p0  = *(const float4*)&PE[d * 128 + pbase];
            float4 p1  = *(const float4*)&PE[d * 128 + pbase + 4];
            float qa[4]  = {qv.x, qv.y, qv.z, qv.w};
            float kb[4]  = {kv4.x, kv4.y, kv4.z, kv4.w};
            float pe8[8] = {p0.x, p0.y, p0.z, p0.w, p1.x, p1.y, p1.z, p1.w};
#pragma unroll
            for (int a = 0; a < 4; ++a)
#pragma unroll
                for (int b = 0; b < 4; ++b)
                    s[a][b] = fmaf(qa[a], kb[b] + pe8[3 + b - a], s[a][b]);
        }

        // scale + causal mask
#pragma unroll
        for (int a = 0; a < 4; ++a)
#pragma unroll
            for (int b = 0; b < 4; ++b) {
                float v = s[a][b] * 0.125f;
                int kg = k0 + c + b;
                int qg = q0 + r + a;
                s[a][b] = (kg > qg + 1280) ? -1e30f : v;
            }

        // online softmax (16-lane row reductions)
#pragma unroll
        for (int a = 0; a < 4; ++a) {
            float mx = fmaxf(fmaxf(s[a][0], s[a][1]), fmaxf(s[a][2], s[a][3]));
#pragma unroll
            for (int o = 1; o < 16; o <<= 1)
                mx = fmaxf(mx, __shfl_xor_sync(0xffffffffu, mx, o));
            float mnew = fmaxf(mrun[a], mx);
            float alpha = __expf(mrun[a] - mnew);
            float p4[4]; float ssum = 0.f;
#pragma unroll
            for (int b = 0; b < 4; ++b) {
                float p = __expf(s[a][b] - mnew);
                p4[b] = p; ssum += p;
            }
#pragma unroll
            for (int o = 1; o < 16; o <<= 1)
                ssum += __shfl_xor_sync(0xffffffffu, ssum, o);
            lrun[a] = lrun[a] * alpha + ssum;
            mrun[a] = mnew;
#pragma unroll
            for (int b = 0; b < 4; ++b) O[a][b] *= alpha;
#pragma unroll
            for (int b = 0; b < 4; ++b) Pt[(c + b) * 68 + (r + a)] = p4[b];
        }
        __syncthreads();

        // --- O += P·V ---
#pragma unroll 16
        for (int kj = 0; kj < 64; ++kj) {
            float4 pv = *(const float4*)&Pt[kj * 68 + r];
            float4 vv = *(const float4*)&Vs[kj * 68 + c];
            float pa[4] = {pv.x, pv.y, pv.z, pv.w};
            float vb[4] = {vv.x, vv.y, vv.z, vv.w};
#pragma unroll
            for (int a = 0; a < 4; ++a)
#pragma unroll
                for (int b = 0; b < 4; ++b)
                    O[a][b] = fmaf(pa[a], vb[b], O[a][b]);
        }
    }

#pragma unroll
    for (int a = 0; a < 4; ++a) {
        float inv = 1.f / lrun[a];
        float4 v;
        v.x = O[a][0] * inv; v.y = O[a][1] * inv;
        v.z = O[a][2] * inv; v.w = O[a][3] * inv;
        *(float4*)&g_ao[((size_t)(bz * 1024 + q0 + r + a)) * 1024 + h * 64 + c] = v;
    }
}

// ---------------------------------------------------------------------------
extern "C" void kernel_launch(void* const* d_in, const int* in_sizes, int n_in,
                              void* d_out, int out_size)
{
    (void)in_sizes; (void)n_in; (void)out_size;
    const float* x     = (const float*)d_in[0];
    const float* memp  = (const float*)d_in[1];
    const float* cmemp = (const float*)d_in[2];
    const float* pos   = (const float*)d_in[3];
    // d_in[4] = input_mask (all True by construction; causal mask only)
    const float* Wq    = (const float*)d_in[5];
    const float* Wkv   = (const float*)d_in[6];
    const float* Wout  = (const float*)d_in[7];
    const float* bout  = (const float*)d_in[8];
    const float* convw = (const float*)d_in[9];
    const float* convb = (const float*)d_in[10];
    float* out = (float*)d_out;

    cudaFuncSetAttribute(attn_kernel,
                         cudaFuncAttributeMaxDynamicSharedMemorySize, 102400);

    dim3 blk(256);
    // q = x @ Wq^T                                  (M=4096, N=1024, K=1024)
    gemm_tpl<0><<<dim3(8, 32), blk>>>(x, nullptr, nullptr, Wq, nullptr, nullptr, 1024, 1024);
    // kv = [cmem;mem;x] @ Wkv^T                     (M=9216, N=2048, K=1024)
    gemm_tpl<1><<<dim3(16, 72), blk>>>(x, memp, cmemp, Wkv, nullptr, nullptr, 1024, 2048);
    // attention
    attn_kernel<<<dim3(16, 16, 4), blk, 102400>>>(pos);
    // logits = ao @ Wout^T + bout  -> d_out[0 : 4M)
    gemm_tpl<2><<<dim3(8, 32), blk>>>(nullptr, nullptr, nullptr, Wout, bout, out, 1024, 1024);
    // new_mem = x  -> d_out[4M : 8M)
    cudaMemcpyAsync(out + 4194304, x, (size_t)4194304 * sizeof(float),
                    cudaMemcpyDeviceToDevice, 0);
    // new_cmem = conv(mem) -> d_out[8M : 9M)
    transpose_w<<<dim3(4, 4096), blk>>>(convw);
    gemm_tpl<3><<<dim3(8, 8), blk>>>(nullptr, memp, nullptr, nullptr, convb,
                                     out + 8388608, 4096, 1024);
}

// round 5
// speedup vs baseline: 2.1735x; 2.1735x over previous
#include <cuda_runtime.h>
#include <cuda_bf16.h>
#include <cstdint>

// ---------------------------------------------------------------------------
// B=4, T=1024, DIM=1024, HEADS=16, DH=64, MEM=1024, CMEM=256, KV=2304,
// TOTAL_MEM=1280, scale=1/8.
// Outputs: logits (4M) | new_mem==x (4M) | new_cmem==conv(mem) (1M) floats.
// GEMMs: warp-level mma.sync bf16x3 (hi/lo split, fp32 accum) — base-ISA only
// (harness targets sm_103 without the 'a' suffix; tcgen05 unavailable).
// Attention: fp32 flash kernel (unchanged from the passing R2 version).
// ---------------------------------------------------------------------------

// fp32 scratch
__device__ float g_q [4u * 1024u * 1024u];
__device__ float g_kv[4u * 2304u * 2048u];
__device__ float g_ao[4u * 1024u * 1024u];

// bf16 hi/lo split scratch
__device__ __nv_bfloat16 g_xhi[4u*1024u*1024u], g_xlo[4u*1024u*1024u];
__device__ __nv_bfloat16 g_mhi[4u*1024u*1024u], g_mlo[4u*1024u*1024u];
__device__ __nv_bfloat16 g_chi[4u*256u*1024u],  g_clo[4u*256u*1024u];
__device__ __nv_bfloat16 g_ahi[4u*1024u*1024u], g_alo[4u*1024u*1024u];
__device__ __nv_bfloat16 g_wqh[1024u*1024u],    g_wql[1024u*1024u];
__device__ __nv_bfloat16 g_wkh[2048u*1024u],    g_wkl[2048u*1024u];
__device__ __nv_bfloat16 g_woh[1024u*1024u],    g_wol[1024u*1024u];
__device__ __nv_bfloat16 g_wch[1024u*4096u],    g_wcl[1024u*4096u];

// ---------------------------------------------------------------------------
// PTX helpers (all base-ISA: ldmatrix / mma.sync / cp.async)
// ---------------------------------------------------------------------------
__device__ __forceinline__ uint32_t smem_u32(const void* p) {
    return (uint32_t)__cvta_generic_to_shared((void*)p);
}
__device__ __forceinline__ void cp16(uint32_t s, const void* g) {
    asm volatile("cp.async.cg.shared.global [%0], [%1], 16;" :: "r"(s), "l"(g));
}
__device__ __forceinline__ void cp_commit() {
    asm volatile("cp.async.commit_group;" ::: "memory");
}
__device__ __forceinline__ void ldsm4(uint32_t& r0, uint32_t& r1,
                                      uint32_t& r2, uint32_t& r3, uint32_t a) {
    asm volatile("ldmatrix.sync.aligned.m8n8.x4.shared.b16 {%0,%1,%2,%3}, [%4];"
                 : "=r"(r0), "=r"(r1), "=r"(r2), "=r"(r3) : "r"(a));
}
__device__ __forceinline__ void mma16816(float* c, uint32_t a0, uint32_t a1,
                                         uint32_t a2, uint32_t a3,
                                         uint32_t b0, uint32_t b1) {
    asm volatile(
        "mma.sync.aligned.m16n8k16.row.col.f32.bf16.bf16.f32 "
        "{%0,%1,%2,%3}, {%4,%5,%6,%7}, {%8,%9}, {%0,%1,%2,%3};"
        : "+f"(c[0]), "+f"(c[1]), "+f"(c[2]), "+f"(c[3])
        : "r"(a0), "r"(a1), "r"(a2), "r"(a3), "r"(b0), "r"(b1));
}

// ---------------------------------------------------------------------------
// fp32 -> (hi, lo) bf16 split.  SEL: 0=x 1=mem 2=cmem 3=Wq 4=Wkv 5=Wout 6=g_ao
// ---------------------------------------------------------------------------
template<int SEL>
__global__ __launch_bounds__(256)
void split_k(const float* __restrict__ s, int n4)
{
    __nv_bfloat16 *hi, *lo;
    if      (SEL == 0) { hi = g_xhi; lo = g_xlo; }
    else if (SEL == 1) { hi = g_mhi; lo = g_mlo; }
    else if (SEL == 2) { hi = g_chi; lo = g_clo; }
    else if (SEL == 3) { hi = g_wqh; lo = g_wql; }
    else if (SEL == 4) { hi = g_wkh; lo = g_wkl; }
    else if (SEL == 5) { hi = g_woh; lo = g_wol; }
    else               { hi = g_ahi; lo = g_alo; s = g_ao; }

    int i = blockIdx.x * 256 + threadIdx.x;
    if (i >= n4) return;
    float4 v = ((const float4*)s)[i];
    float vv[4] = {v.x, v.y, v.z, v.w};
    __nv_bfloat162 h2[2], l2[2];
#pragma unroll
    for (int j = 0; j < 2; ++j) {
        __nv_bfloat16 ha = __float2bfloat16(vv[2*j]);
        __nv_bfloat16 hb = __float2bfloat16(vv[2*j+1]);
        __nv_bfloat16 la = __float2bfloat16(vv[2*j]   - __bfloat162float(ha));
        __nv_bfloat16 lb = __float2bfloat16(vv[2*j+1] - __bfloat162float(hb));
        h2[j] = __nv_bfloat162(ha, hb);
        l2[j] = __nv_bfloat162(la, lb);
    }
    ((__nv_bfloat162*)(hi + 4*(size_t)i))[0] = h2[0];
    ((__nv_bfloat162*)(hi + 4*(size_t)i))[1] = h2[1];
    ((__nv_bfloat162*)(lo + 4*(size_t)i))[0] = l2[0];
    ((__nv_bfloat162*)(lo + 4*(size_t)i))[1] = l2[1];
}

// conv weight gather+split: B[n][k] = conv_w[n][i][r], k = r*1024 + i
__global__ __launch_bounds__(256)
void conv_split(const float* __restrict__ w)
{
    int t = blockIdx.x * 256 + threadIdx.x;        // 0 .. 4M-1
    int n = t >> 12, k = t & 4095;
    int i = k & 1023, r = k >> 10;
    float v = w[(size_t)n * 4096 + i * 4 + r];
    __nv_bfloat16 h = __float2bfloat16(v);
    g_wch[t] = h;
    g_wcl[t] = __float2bfloat16(v - __bfloat162float(h));
}

// ---------------------------------------------------------------------------
// mma.sync bf16x3 GEMM: C[M,N] = A[M,K] * B[N,K]^T (+bias)
// Block tile 128x128, BK=32, 8 warps (warp tile 32x64), 2-stage cp.async.
// Smem per stage: Ah|Al|Bh|Bl, each [128][32] bf16 padded to 40 (80B rows).
// MODE 0: q = x@Wq^T -> g_q    MODE 1: kv = gather@Wkv^T -> g_kv
// MODE 2: logits = ao@Wout^T + bout -> C    MODE 3: conv -> C
// ---------------------------------------------------------------------------
#define STG_BYTES 40960          // 4 * 128*40*2
#define MAT_BYTES 10240

template<int MODE>
__global__ __launch_bounds__(256, 2)
void gemm_mma(const float* __restrict__ bias, float* __restrict__ Cparam,
              int K, int ldc)
{
    extern __shared__ char smg[];
    const uint32_t sm0 = smem_u32(smg);

    const int tid = threadIdx.x;
    const int lane = tid & 31, wid = tid >> 5;
    const int m0 = blockIdx.y * 128;
    const int n0 = blockIdx.x * 128;
    const int wm = (wid & 3) * 32;      // warp row offset in tile
    const int wn = (wid >> 2) * 64;     // warp col offset in tile

    // ---- per-thread global row pointers (2 rows each for A and B) ----
    const __nv_bfloat16 *ah[2], *al[2], *bh[2], *bl[2];
    uint32_t soff[2];
    const int c16 = tid & 3;            // 16B chunk within a 64B row
#pragma unroll
    for (int i = 0; i < 2; ++i) {
        int row = (tid + i * 256) >> 2;           // 0..127
        soff[i] = (uint32_t)(row * 80 + c16 * 16);
        int mg = m0 + row;
        const __nv_bfloat16 *hb, *lb; size_t off;
        if (MODE == 0)      { hb = g_xhi; lb = g_xlo; off = (size_t)mg * 1024; }
        else if (MODE == 1) {
            int b = mg / 2304, s = mg - b * 2304;
            if (s < 256)       { hb = g_chi; lb = g_clo; off = ((size_t)b*256  + s)        * 1024; }
            else if (s < 1280) { hb = g_mhi; lb = g_mlo; off = ((size_t)b*1024 + (s-256))  * 1024; }
            else               { hb = g_xhi; lb = g_xlo; off = ((size_t)b*1024 + (s-1280)) * 1024; }
        }
        else if (MODE == 2) { hb = g_ahi; lb = g_alo; off = (size_t)mg * 1024; }
        else { int b = mg >> 8; int t4 = (mg & 255) << 2;
               hb = g_mhi; lb = g_mlo; off = ((size_t)b*1024 + t4) * 1024; }
        ah[i] = hb + off; al[i] = lb + off;

        const __nv_bfloat16 *Bh, *Bl;
        if      (MODE == 0) { Bh = g_wqh; Bl = g_wql; }
        else if (MODE == 1) { Bh = g_wkh; Bl = g_wkl; }
        else if (MODE == 2) { Bh = g_woh; Bl = g_wol; }
        else                { Bh = g_wch; Bl = g_wcl; }
        size_t boff = (size_t)(n0 + row) * K;
        bh[i] = Bh + boff; bl[i] = Bl + boff;
    }

    float acc[2][8][4];
#pragma unroll
    for (int mt = 0; mt < 2; ++mt)
#pragma unroll
        for (int nt = 0; nt < 8; ++nt)
#pragma unroll
            for (int e = 0; e < 4; ++e) acc[mt][nt][e] = 0.f;

    const int nch = K >> 5;

    // ---- stage loader ----
    auto load_stage = [&](int ch, int s) {
        uint32_t sb = sm0 + (uint32_t)s * STG_BYTES;
        int k0 = ch << 5;
        int ge = k0 + c16 * 8;
#pragma unroll
        for (int i = 0; i < 2; ++i) {
            cp16(sb + 0*MAT_BYTES + soff[i], ah[i] + ge);
            cp16(sb + 1*MAT_BYTES + soff[i], al[i] + ge);
            cp16(sb + 2*MAT_BYTES + soff[i], bh[i] + ge);
            cp16(sb + 3*MAT_BYTES + soff[i], bl[i] + ge);
        }
        cp_commit();
    };

    load_stage(0, 0);

    const int quad = lane >> 3, rin = lane & 7;
    for (int ch = 0; ch < nch; ++ch) {
        bool more = (ch + 1 < nch);
        if (more) load_stage(ch + 1, (ch + 1) & 1);
        if (more) asm volatile("cp.async.wait_group 1;" ::: "memory");
        else      asm volatile("cp.async.wait_group 0;" ::: "memory");
        __syncthreads();

        uint32_t sb = sm0 + (uint32_t)(ch & 1) * STG_BYTES;
        const uint32_t aAh = sb, aAl = sb + MAT_BYTES;
        const uint32_t aBh = sb + 2*MAT_BYTES, aBl = sb + 3*MAT_BYTES;

#pragma unroll
        for (int pass = 0; pass < 3; ++pass) {
            uint32_t ab = (pass == 2) ? aAl : aAh;
            uint32_t bb = (pass == 1) ? aBl : aBh;
#pragma unroll
            for (int ks = 0; ks < 2; ++ks) {
                int k0 = ks * 16;
                // B fragments: 8 n-tiles, loaded 2 per ldmatrix.x4
                uint32_t Bf[8][2];
#pragma unroll
                for (int p = 0; p < 4; ++p) {
                    int brow = wn + p * 16 + (quad >> 1) * 8 + rin;
                    int bcol = k0 + (quad & 1) * 8;
                    ldsm4(Bf[2*p][0], Bf[2*p][1], Bf[2*p+1][0], Bf[2*p+1][1],
                          bb + (uint32_t)(brow * 80 + bcol * 2));
                }
#pragma unroll
                for (int mt = 0; mt < 2; ++mt) {
                    int arow = wm + mt * 16 + (quad & 1) * 8 + rin;
                    int acol = k0 + (quad >> 1) * 8;
                    uint32_t a0, a1, a2, a3;
                    ldsm4(a0, a1, a2, a3, ab + (uint32_t)(arow * 80 + acol * 2));
#pragma unroll
                    for (int nt = 0; nt < 8; ++nt)
                        mma16816(acc[mt][nt], a0, a1, a2, a3, Bf[nt][0], Bf[nt][1]);
                }
            }
        }
        __syncthreads();
    }

    // ---- epilogue: direct fragment stores ----
    float* Cp = (MODE == 0) ? g_q : (MODE == 1) ? g_kv : Cparam;
    const int qrow = lane >> 2, rr = lane & 3;
#pragma unroll
    for (int mt = 0; mt < 2; ++mt) {
        int r0g = m0 + wm + mt * 16 + qrow;
#pragma unroll
        for (int nt = 0; nt < 8; ++nt) {
            int col = n0 + wn + nt * 8 + rr * 2;
            float b0 = 0.f, b1 = 0.f;
            if (MODE >= 2) { b0 = bias[col]; b1 = bias[col + 1]; }
            float2 v0 = make_float2(acc[mt][nt][0] + b0, acc[mt][nt][1] + b1);
            float2 v1 = make_float2(acc[mt][nt][2] + b0, acc[mt][nt][3] + b1);
            *(float2*)&Cp[(size_t)r0g * ldc + col]       = v0;
            *(float2*)&Cp[(size_t)(r0g + 8) * ldc + col] = v1;
        }
    }
}

// ---------------------------------------------------------------------------
// Flash attention with Transformer-XL rel-pos shift (unchanged, fp32).
// ---------------------------------------------------------------------------
__global__ __launch_bounds__(256)
void attn_kernel(const float* __restrict__ pos_emb)
{
    extern __shared__ float sm[];
    float* Qt = sm;                 // [64][68] Qt[d][qi]
    float* Kt = sm + 64 * 68;       // [64][68] Kt[d][kj]
    float* Vs = sm + 2 * 64 * 68;   // [64][68] Vs[kj][d]
    float* Pt = sm + 3 * 64 * 68;   // [64][68] Pt[kj][qi]
    float* PE = sm + 4 * 64 * 68;   // [64][128] PE[d][p]

    const int tid = threadIdx.x;
    const int qt = blockIdx.x, h = blockIdx.y, bz = blockIdx.z;
    const int q0 = qt * 64;
    const int r = (tid >> 4) << 2;
    const int c = (tid & 15) << 2;
    const int pbase = 60 + c - r;

    for (int idx = tid; idx < 1024; idx += 256) {
        int qi = idx >> 4, d4 = (idx & 15) << 2;
        float4 v = *(const float4*)&g_q[((size_t)(bz * 1024 + q0 + qi)) * 1024 + h * 64 + d4];
        Qt[(d4 + 0) * 68 + qi] = v.x; Qt[(d4 + 1) * 68 + qi] = v.y;
        Qt[(d4 + 2) * 68 + qi] = v.z; Qt[(d4 + 3) * 68 + qi] = v.w;
    }

    float O[4][4];
    float mrun[4], lrun[4];
#pragma unroll
    for (int a = 0; a < 4; ++a) {
        mrun[a] = -1e30f; lrun[a] = 0.f;
#pragma unroll
        for (int b = 0; b < 4; ++b) O[a][b] = 0.f;
    }

    const int kend = q0 + 1344;

    for (int k0 = 0; k0 < kend; k0 += 64) {
        __syncthreads();

        for (int idx = tid; idx < 1024; idx += 256) {
            int kj = idx >> 4, d4 = (idx & 15) << 2;
            size_t base = ((size_t)(bz * 2304 + k0 + kj)) * 2048 + h * 64;
            float4 kv4 = *(const float4*)&g_kv[base + d4];
            Kt[(d4 + 0) * 68 + kj] = kv4.x; Kt[(d4 + 1) * 68 + kj] = kv4.y;
            Kt[(d4 + 2) * 68 + kj] = kv4.z; Kt[(d4 + 3) * 68 + kj] = kv4.w;
            float4 vv = *(const float4*)&g_kv[base + 1024 + d4];
            *(float4*)&Vs[kj * 68 + d4] = vv;
        }
        int c_base = k0 + 960 - q0;
        for (int idx = tid; idx < 2048; idx += 256) {
            int p = idx >> 4, d4 = (idx & 15) << 2;
            int crow = c_base + p;
            float4 v = make_float4(0.f, 0.f, 0.f, 0.f);
            if (p < 127 && crow < 2304)
                v = *(const float4*)&pos_emb[((size_t)h * 2304 + crow) * 64 + d4];
            PE[(d4 + 0) * 128 + p] = v.x; PE[(d4 + 1) * 128 + p] = v.y;
            PE[(d4 + 2) * 128 + p] = v.z; PE[(d4 + 3) * 128 + p] = v.w;
        }
        __syncthreads();

        float s[4][4];
#pragma unroll
        for (int a = 0; a < 4; ++a)
#pragma unroll
            for (int b = 0; b < 4; ++b) s[a][b] = 0.f;

#pragma unroll 16
        for (int d = 0; d < 64; ++d) {
            float4 qv  = *(const float4*)&Qt[d * 68 + r];
            float4 kv4 = *(const float4*)&Kt[d * 68 + c];
            float4 p0  = *(const float4*)&PE[d * 128 + pbase];
            float4 p1  = *(const float4*)&PE[d * 128 + pbase + 4];
            float qa[4]  = {qv.x, qv.y, qv.z, qv.w};
            float kb[4]  = {kv4.x, kv4.y, kv4.z, kv4.w};
            float pe8[8] = {p0.x, p0.y, p0.z, p0.w, p1.x, p1.y, p1.z, p1.w};
#pragma unroll
            for (int a = 0; a < 4; ++a)
#pragma unroll
                for (int b = 0; b < 4; ++b)
                    s[a][b] = fmaf(qa[a], kb[b] + pe8[3 + b - a], s[a][b]);
        }

#pragma unroll
        for (int a = 0; a < 4; ++a)
#pragma unroll
            for (int b = 0; b < 4; ++b) {
                float v = s[a][b] * 0.125f;
                int kg = k0 + c + b;
                int qg = q0 + r + a;
                s[a][b] = (kg > qg + 1280) ? -1e30f : v;
            }

#pragma unroll
        for (int a = 0; a < 4; ++a) {
            float mx = fmaxf(fmaxf(s[a][0], s[a][1]), fmaxf(s[a][2], s[a][3]));
#pragma unroll
            for (int o = 1; o < 16; o <<= 1)
                mx = fmaxf(mx, __shfl_xor_sync(0xffffffffu, mx, o));
            float mnew = fmaxf(mrun[a], mx);
            float alpha = __expf(mrun[a] - mnew);
            float p4[4]; float ssum = 0.f;
#pragma unroll
            for (int b = 0; b < 4; ++b) {
                float p = __expf(s[a][b] - mnew);
                p4[b] = p; ssum += p;
            }
#pragma unroll
            for (int o = 1; o < 16; o <<= 1)
                ssum += __shfl_xor_sync(0xffffffffu, ssum, o);
            lrun[a] = lrun[a] * alpha + ssum;
            mrun[a] = mnew;
#pragma unroll
            for (int b = 0; b < 4; ++b) O[a][b] *= alpha;
#pragma unroll
            for (int b = 0; b < 4; ++b) Pt[(c + b) * 68 + (r + a)] = p4[b];
        }
        __syncthreads();

#pragma unroll 16
        for (int kj = 0; kj < 64; ++kj) {
            float4 pv = *(const float4*)&Pt[kj * 68 + r];
            float4 vv = *(const float4*)&Vs[kj * 68 + c];
            float pa[4] = {pv.x, pv.y, pv.z, pv.w};
            float vb[4] = {vv.x, vv.y, vv.z, vv.w};
#pragma unroll
            for (int a = 0; a < 4; ++a)
#pragma unroll
                for (int b = 0; b < 4; ++b)
                    O[a][b] = fmaf(pa[a], vb[b], O[a][b]);
        }
    }

#pragma unroll
    for (int a = 0; a < 4; ++a) {
        float inv = 1.f / lrun[a];
        float4 v;
        v.x = O[a][0] * inv; v.y = O[a][1] * inv;
        v.z = O[a][2] * inv; v.w = O[a][3] * inv;
        *(float4*)&g_ao[((size_t)(bz * 1024 + q0 + r + a)) * 1024 + h * 64 + c] = v;
    }
}

// ---------------------------------------------------------------------------
extern "C" void kernel_launch(void* const* d_in, const int* in_sizes, int n_in,
                              void* d_out, int out_size)
{
    (void)in_sizes; (void)n_in; (void)out_size;
    const float* x     = (const float*)d_in[0];
    const float* memp  = (const float*)d_in[1];
    const float* cmemp = (const float*)d_in[2];
    const float* pos   = (const float*)d_in[3];
    // d_in[4] = input_mask (all True; only causal mask matters)
    const float* Wq    = (const float*)d_in[5];
    const float* Wkv   = (const float*)d_in[6];
    const float* Wout  = (const float*)d_in[7];
    const float* bout  = (const float*)d_in[8];
    const float* convw = (const float*)d_in[9];
    const float* convb = (const float*)d_in[10];
    float* out = (float*)d_out;

    const int GSM = 2 * STG_BYTES;   // 81920
    cudaFuncSetAttribute(gemm_mma<0>, cudaFuncAttributeMaxDynamicSharedMemorySize, GSM);
    cudaFuncSetAttribute(gemm_mma<1>, cudaFuncAttributeMaxDynamicSharedMemorySize, GSM);
    cudaFuncSetAttribute(gemm_mma<2>, cudaFuncAttributeMaxDynamicSharedMemorySize, GSM);
    cudaFuncSetAttribute(gemm_mma<3>, cudaFuncAttributeMaxDynamicSharedMemorySize, GSM);
    cudaFuncSetAttribute(attn_kernel, cudaFuncAttributeMaxDynamicSharedMemorySize, 102400);

    dim3 blk(256);
    // hi/lo splits
    split_k<0><<<4096, blk>>>(x,     1048576);
    split_k<1><<<4096, blk>>>(memp,  1048576);
    split_k<2><<<1024, blk>>>(cmemp,  262144);
    split_k<3><<<1024, blk>>>(Wq,     262144);
    split_k<4><<<2048, blk>>>(Wkv,    524288);
    split_k<5><<<1024, blk>>>(Wout,   262144);
    conv_split<<<16384, blk>>>(convw);

    // q = x @ Wq^T                 (M=4096, N=1024, K=1024)
    gemm_mma<0><<<dim3(8, 32), blk, GSM>>>(nullptr, nullptr, 1024, 1024);
    // kv = [cmem;mem;x] @ Wkv^T    (M=9216, N=2048, K=1024)
    gemm_mma<1><<<dim3(16, 72), blk, GSM>>>(nullptr, nullptr, 1024, 2048);
    // attention (fp32)
    attn_kernel<<<dim3(16, 16, 4), blk, 102400>>>(pos);
    // split attention output, then logits = ao @ Wout^T + bout
    split_k<6><<<4096, blk>>>(nullptr, 1048576);
    gemm_mma<2><<<dim3(8, 32), blk, GSM>>>(bout, out, 1024, 1024);
    // new_mem = x
    cudaMemcpyAsync(out + 4194304, x, (size_t)4194304 * sizeof(float),
                    cudaMemcpyDeviceToDevice, 0);
    // new_cmem = conv(mem)         (M=1024, N=1024, K=4096)
    gemm_mma<3><<<dim3(8, 8), blk, GSM>>>(convb, out + 8388608, 4096, 1024);
}

// round 6
// speedup vs baseline: 4.1812x; 1.9237x over previous
#include <cuda_runtime.h>
#include <cuda_bf16.h>
#include <cstdint>

// ---------------------------------------------------------------------------
// B=4, T=1024, DIM=1024, HEADS=16, DH=64, MEM=1024, CMEM=256, KV=2304,
// TOTAL_MEM=1280, scale=1/8.
// Outputs: logits (4M) | new_mem==x (4M) | new_cmem==conv(mem) (1M) floats.
// Everything dense on mma.sync bf16x3 (hi/lo split, fp32 accum).
// Pos term precomputed: PD[b,h,i,j] = q_i . pe[j+1023-i]  (GEMM + shifted scatter)
// ---------------------------------------------------------------------------

__device__ float g_pd[150994944ull];    // [b][h][1024][2304] fp32, 604MB

__device__ __nv_bfloat16 g_xhi[4194304],  g_xlo[4194304];
__device__ __nv_bfloat16 g_mhi[4194304],  g_mlo[4194304];
__device__ __nv_bfloat16 g_chi[1048576],  g_clo[1048576];
__device__ __nv_bfloat16 g_wqh[1048576],  g_wql[1048576];
__device__ __nv_bfloat16 g_wkh[2097152],  g_wkl[2097152];
__device__ __nv_bfloat16 g_woh[1048576],  g_wol[1048576];
__device__ __nv_bfloat16 g_wch[4194304],  g_wcl[4194304];
__device__ __nv_bfloat16 g_peh[2359296],  g_pel[2359296];
__device__ __nv_bfloat16 g_qh [4194304],  g_ql [4194304];
__device__ __nv_bfloat16 g_kvh[18874368], g_kvl[18874368];
__device__ __nv_bfloat16 g_ahi[4194304],  g_alo[4194304];

// ---------------------------------------------------------------------------
// PTX helpers (base-ISA: ldmatrix / mma.sync / cp.async)
// ---------------------------------------------------------------------------
__device__ __forceinline__ uint32_t smem_u32(const void* p) {
    return (uint32_t)__cvta_generic_to_shared((void*)p);
}
__device__ __forceinline__ void cp16(uint32_t s, const void* g) {
    asm volatile("cp.async.cg.shared.global [%0], [%1], 16;" :: "r"(s), "l"(g));
}
__device__ __forceinline__ void cp_commit() {
    asm volatile("cp.async.commit_group;" ::: "memory");
}
__device__ __forceinline__ void ldsm4(uint32_t& r0, uint32_t& r1,
                                      uint32_t& r2, uint32_t& r3, uint32_t a) {
    asm volatile("ldmatrix.sync.aligned.m8n8.x4.shared.b16 {%0,%1,%2,%3}, [%4];"
                 : "=r"(r0), "=r"(r1), "=r"(r2), "=r"(r3) : "r"(a));
}
__device__ __forceinline__ void ldsm4t(uint32_t& r0, uint32_t& r1,
                                       uint32_t& r2, uint32_t& r3, uint32_t a) {
    asm volatile("ldmatrix.sync.aligned.m8n8.x4.trans.shared.b16 {%0,%1,%2,%3}, [%4];"
                 : "=r"(r0), "=r"(r1), "=r"(r2), "=r"(r3) : "r"(a));
}
__device__ __forceinline__ void mma16816(float* c, uint32_t a0, uint32_t a1,
                                         uint32_t a2, uint32_t a3,
                                         uint32_t b0, uint32_t b1) {
    asm volatile(
        "mma.sync.aligned.m16n8k16.row.col.f32.bf16.bf16.f32 "
        "{%0,%1,%2,%3}, {%4,%5,%6,%7}, {%8,%9}, {%0,%1,%2,%3};"
        : "+f"(c[0]), "+f"(c[1]), "+f"(c[2]), "+f"(c[3])
        : "r"(a0), "r"(a1), "r"(a2), "r"(a3), "r"(b0), "r"(b1));
}
__device__ __forceinline__ uint32_t pack2(__nv_bfloat16 a, __nv_bfloat16 b) {
    __nv_bfloat162 t(a, b);
    return *(uint32_t*)&t;
}

// ---------------------------------------------------------------------------
// fp32 -> (hi, lo) bf16 splits.  SEL: 0=x 1=mem 2=cmem 3=Wq 4=Wkv 5=Wout
// ---------------------------------------------------------------------------
template<int SEL>
__global__ __launch_bounds__(256)
void split_k(const float* __restrict__ s, int n4)
{
    __nv_bfloat16 *hi, *lo;
    if      (SEL == 0) { hi = g_xhi; lo = g_xlo; }
    else if (SEL == 1) { hi = g_mhi; lo = g_mlo; }
    else if (SEL == 2) { hi = g_chi; lo = g_clo; }
    else if (SEL == 3) { hi = g_wqh; lo = g_wql; }
    else if (SEL == 4) { hi = g_wkh; lo = g_wkl; }
    else               { hi = g_woh; lo = g_wol; }

    int i = blockIdx.x * 256 + threadIdx.x;
    if (i >= n4) return;
    float4 v = ((const float4*)s)[i];
    float vv[4] = {v.x, v.y, v.z, v.w};
#pragma unroll
    for (int j = 0; j < 2; ++j) {
        __nv_bfloat16 ha = __float2bfloat16(vv[2*j]);
        __nv_bfloat16 hb = __float2bfloat16(vv[2*j+1]);
        __nv_bfloat16 la = __float2bfloat16(vv[2*j]   - __bfloat162float(ha));
        __nv_bfloat16 lb = __float2bfloat16(vv[2*j+1] - __bfloat162float(hb));
        *(uint32_t*)&hi[4*(size_t)i + 2*j] = pack2(ha, hb);
        *(uint32_t*)&lo[4*(size_t)i + 2*j] = pack2(la, lb);
    }
}

__global__ __launch_bounds__(256)
void pe_split(const float* __restrict__ pe)
{
    int i = blockIdx.x * 256 + threadIdx.x;     // over 589824 float4
    if (i >= 589824) return;
    float4 v = ((const float4*)pe)[i];
    float vv[4] = {v.x, v.y, v.z, v.w};
#pragma unroll
    for (int j = 0; j < 2; ++j) {
        __nv_bfloat16 ha = __float2bfloat16(vv[2*j]);
        __nv_bfloat16 hb = __float2bfloat16(vv[2*j+1]);
        __nv_bfloat16 la = __float2bfloat16(vv[2*j]   - __bfloat162float(ha));
        __nv_bfloat16 lb = __float2bfloat16(vv[2*j+1] - __bfloat162float(hb));
        *(uint32_t*)&g_peh[4*(size_t)i + 2*j] = pack2(ha, hb);
        *(uint32_t*)&g_pel[4*(size_t)i + 2*j] = pack2(la, lb);
    }
}

// conv weight gather+split: B[n][k] = conv_w[n][i][r], k = r*1024 + i
__global__ __launch_bounds__(256)
void conv_split(const float* __restrict__ w)
{
    int t = blockIdx.x * 256 + threadIdx.x;        // 0 .. 4M-1
    int n = t >> 12, k = t & 4095;
    int i = k & 1023, r = k >> 10;
    float v = w[(size_t)n * 4096 + i * 4 + r];
    __nv_bfloat16 h = __float2bfloat16(v);
    g_wch[t] = h;
    g_wcl[t] = __float2bfloat16(v - __bfloat162float(h));
}

// ---------------------------------------------------------------------------
// mma.sync bf16x3 GEMM: C[M,N] = A[M,K] * B[N,K]^T (+bias)
// Block 128x128, BK=32, 8 warps (warp tile 32x64), 2-stage cp.async.
// MODE 0: q -> g_qh/g_ql (bf16 out)   MODE 1: kv -> g_kvh/g_kvl (bf16 out)
// MODE 2: logits = ao@Wout^T + bout -> C (fp32)   MODE 3: conv -> C (fp32)
// ---------------------------------------------------------------------------
#define STG_BYTES 40960          // 4 * 128*40*2
#define MAT_BYTES 10240

template<int MODE>
__global__ __launch_bounds__(256, 2)
void gemm_mma(const float* __restrict__ bias, float* __restrict__ Cparam,
              int K, int ldc)
{
    extern __shared__ char smg[];
    const uint32_t sm0 = smem_u32(smg);

    const int tid = threadIdx.x;
    const int lane = tid & 31, wid = tid >> 5;
    const int m0 = blockIdx.y * 128;
    const int n0 = blockIdx.x * 128;
    const int wm = (wid & 3) * 32;
    const int wn = (wid >> 2) * 64;

    const __nv_bfloat16 *ah[2], *al[2], *bh[2], *bl[2];
    uint32_t soff[2];
    const int c16 = tid & 3;
#pragma unroll
    for (int i = 0; i < 2; ++i) {
        int row = (tid + i * 256) >> 2;
        soff[i] = (uint32_t)(row * 80 + c16 * 16);
        int mg = m0 + row;
        const __nv_bfloat16 *hb, *lb; size_t off;
        if (MODE == 0)      { hb = g_xhi; lb = g_xlo; off = (size_t)mg * 1024; }
        else if (MODE == 1) {
            int b = mg / 2304, s = mg - b * 2304;
            if (s < 256)       { hb = g_chi; lb = g_clo; off = ((size_t)b*256  + s)        * 1024; }
            else if (s < 1280) { hb = g_mhi; lb = g_mlo; off = ((size_t)b*1024 + (s-256))  * 1024; }
            else               { hb = g_xhi; lb = g_xlo; off = ((size_t)b*1024 + (s-1280)) * 1024; }
        }
        else if (MODE == 2) { hb = g_ahi; lb = g_alo; off = (size_t)mg * 1024; }
        else { int b = mg >> 8; int t4 = (mg & 255) << 2;
               hb = g_mhi; lb = g_mlo; off = ((size_t)b*1024 + t4) * 1024; }
        ah[i] = hb + off; al[i] = lb + off;

        const __nv_bfloat16 *Bh, *Bl;
        if      (MODE == 0) { Bh = g_wqh; Bl = g_wql; }
        else if (MODE == 1) { Bh = g_wkh; Bl = g_wkl; }
        else if (MODE == 2) { Bh = g_woh; Bl = g_wol; }
        else                { Bh = g_wch; Bl = g_wcl; }
        size_t boff = (size_t)(n0 + row) * K;
        bh[i] = Bh + boff; bl[i] = Bl + boff;
    }

    float acc[2][8][4];
#pragma unroll
    for (int mt = 0; mt < 2; ++mt)
#pragma unroll
        for (int nt = 0; nt < 8; ++nt)
#pragma unroll
            for (int e = 0; e < 4; ++e) acc[mt][nt][e] = 0.f;

    const int nch = K >> 5;

    auto load_stage = [&](int ch, int s) {
        uint32_t sb = sm0 + (uint32_t)s * STG_BYTES;
        int ge = (ch << 5) + c16 * 8;
#pragma unroll
        for (int i = 0; i < 2; ++i) {
            cp16(sb + 0*MAT_BYTES + soff[i], ah[i] + ge);
            cp16(sb + 1*MAT_BYTES + soff[i], al[i] + ge);
            cp16(sb + 2*MAT_BYTES + soff[i], bh[i] + ge);
            cp16(sb + 3*MAT_BYTES + soff[i], bl[i] + ge);
        }
        cp_commit();
    };

    load_stage(0, 0);

    const int quad = lane >> 3, rin = lane & 7;
    for (int ch = 0; ch < nch; ++ch) {
        bool more = (ch + 1 < nch);
        if (more) load_stage(ch + 1, (ch + 1) & 1);
        if (more) asm volatile("cp.async.wait_group 1;" ::: "memory");
        else      asm volatile("cp.async.wait_group 0;" ::: "memory");
        __syncthreads();

        uint32_t sb = sm0 + (uint32_t)(ch & 1) * STG_BYTES;
        const uint32_t aAh = sb, aAl = sb + MAT_BYTES;
        const uint32_t aBh = sb + 2*MAT_BYTES, aBl = sb + 3*MAT_BYTES;

#pragma unroll
        for (int pass = 0; pass < 3; ++pass) {
            uint32_t ab = (pass == 2) ? aAl : aAh;
            uint32_t bb = (pass == 1) ? aBl : aBh;
#pragma unroll
            for (int ks = 0; ks < 2; ++ks) {
                int k0 = ks * 16;
                uint32_t Bf[8][2];
#pragma unroll
                for (int p = 0; p < 4; ++p) {
                    int brow = wn + p * 16 + (quad >> 1) * 8 + rin;
                    int bcol = k0 + (quad & 1) * 8;
                    ldsm4(Bf[2*p][0], Bf[2*p][1], Bf[2*p+1][0], Bf[2*p+1][1],
                          bb + (uint32_t)(brow * 80 + bcol * 2));
                }
#pragma unroll
                for (int mt = 0; mt < 2; ++mt) {
                    int arow = wm + mt * 16 + (quad & 1) * 8 + rin;
                    int acol = k0 + (quad >> 1) * 8;
                    uint32_t a0, a1, a2, a3;
                    ldsm4(a0, a1, a2, a3, ab + (uint32_t)(arow * 80 + acol * 2));
#pragma unroll
                    for (int nt = 0; nt < 8; ++nt)
                        mma16816(acc[mt][nt], a0, a1, a2, a3, Bf[nt][0], Bf[nt][1]);
                }
            }
        }
        __syncthreads();
    }

    const int qrow = lane >> 2, rr = lane & 3;
    if (MODE <= 1) {
        __nv_bfloat16* Oh = (MODE == 0) ? g_qh : g_kvh;
        __nv_bfloat16* Ol = (MODE == 0) ? g_ql : g_kvl;
#pragma unroll
        for (int mt = 0; mt < 2; ++mt) {
            int r0g = m0 + wm + mt * 16 + qrow;
#pragma unroll
            for (int nt = 0; nt < 8; ++nt) {
                int col = n0 + wn + nt * 8 + rr * 2;
#pragma unroll
                for (int half = 0; half < 2; ++half) {
                    float f0 = acc[mt][nt][2*half], f1 = acc[mt][nt][2*half+1];
                    __nv_bfloat16 h0 = __float2bfloat16(f0);
                    __nv_bfloat16 h1 = __float2bfloat16(f1);
                    __nv_bfloat16 q0 = __float2bfloat16(f0 - __bfloat162float(h0));
                    __nv_bfloat16 q1 = __float2bfloat16(f1 - __bfloat162float(h1));
                    size_t idx = (size_t)(r0g + half * 8) * ldc + col;
                    *(uint32_t*)&Oh[idx] = pack2(h0, h1);
                    *(uint32_t*)&Ol[idx] = pack2(q0, q1);
                }
            }
        }
    } else {
#pragma unroll
        for (int mt = 0; mt < 2; ++mt) {
            int r0g = m0 + wm + mt * 16 + qrow;
#pragma unroll
            for (int nt = 0; nt < 8; ++nt) {
                int col = n0 + wn + nt * 8 + rr * 2;
                float b0 = bias[col], b1 = bias[col + 1];
                float2 v0 = make_float2(acc[mt][nt][0] + b0, acc[mt][nt][1] + b1);
                float2 v1 = make_float2(acc[mt][nt][2] + b0, acc[mt][nt][3] + b1);
                *(float2*)&Cparam[(size_t)r0g * ldc + col]       = v0;
                *(float2*)&Cparam[(size_t)(r0g + 8) * ldc + col] = v1;
            }
        }
    }
}

// ---------------------------------------------------------------------------
// PD GEMM: R[i,c] = q_i . pe_c (bf16x3), scatter to PD[i, j = c-1023+i].
// Block 128x128, K=64 single shot, 8 warps (warp tile 32x64).
// grid = (ctile 18, itile 8, b*16+h 64)
// ---------------------------------------------------------------------------
__global__ __launch_bounds__(256, 2)
void pd_gemm()
{
    extern __shared__ char smem[];
    const uint32_t s0 = smem_u32(smem);
    const uint32_t AH = s0, AL = s0 + 18432, BH = s0 + 36864, BL = s0 + 55296;
    const int tid = threadIdx.x, lane = tid & 31, wid = tid >> 5;
    const int c0 = blockIdx.x * 128, i0 = blockIdx.y * 128;
    const int bh = blockIdx.z;
    const int b = bh >> 4, h = bh & 15;
    const int quad = lane >> 3, rin = lane & 7, orow = lane >> 2, rr = lane & 3;
    const int wm = (wid & 3) * 32, wn = (wid >> 2) * 64;

#pragma unroll
    for (int i = 0; i < 4; ++i) {
        int idx = tid + i * 256;
        int row = idx >> 3, ch = idx & 7;
        uint32_t so = (uint32_t)(row * 144 + ch * 16);
        size_t asrc = ((size_t)(b * 1024 + i0 + row)) * 1024 + h * 64 + ch * 8;
        cp16(AH + so, g_qh + asrc);
        cp16(AL + so, g_ql + asrc);
        size_t bsrc = ((size_t)(h * 2304 + c0 + row)) * 64 + ch * 8;
        cp16(BH + so, g_peh + bsrc);
        cp16(BL + so, g_pel + bsrc);
    }
    cp_commit();
    asm volatile("cp.async.wait_group 0;" ::: "memory");
    __syncthreads();

    float acc[2][8][4];
#pragma unroll
    for (int mt = 0; mt < 2; ++mt)
#pragma unroll
        for (int nt = 0; nt < 8; ++nt)
#pragma unroll
            for (int e = 0; e < 4; ++e) acc[mt][nt][e] = 0.f;

#pragma unroll
    for (int ks = 0; ks < 4; ++ks) {
        uint32_t ahf[2][4], alf[2][4];
#pragma unroll
        for (int mt = 0; mt < 2; ++mt) {
            uint32_t aaddr = (uint32_t)((wm + mt*16 + (quad&1)*8 + rin) * 144
                                        + (ks*16 + (quad>>1)*8) * 2);
            ldsm4(ahf[mt][0], ahf[mt][1], ahf[mt][2], ahf[mt][3], AH + aaddr);
            ldsm4(alf[mt][0], alf[mt][1], alf[mt][2], alf[mt][3], AL + aaddr);
        }
        uint32_t bhf[8][2], blf[8][2];
#pragma unroll
        for (int p = 0; p < 4; ++p) {
            uint32_t baddr = (uint32_t)((wn + p*16 + (quad>>1)*8 + rin) * 144
                                        + (ks*16 + (quad&1)*8) * 2);
            ldsm4(bhf[2*p][0], bhf[2*p][1], bhf[2*p+1][0], bhf[2*p+1][1], BH + baddr);
            ldsm4(blf[2*p][0], blf[2*p][1], blf[2*p+1][0], blf[2*p+1][1], BL + baddr);
        }
#pragma unroll
        for (int mt = 0; mt < 2; ++mt)
#pragma unroll
            for (int nt = 0; nt < 8; ++nt) {
                mma16816(acc[mt][nt], ahf[mt][0],ahf[mt][1],ahf[mt][2],ahf[mt][3],
                         bhf[nt][0], bhf[nt][1]);
                mma16816(acc[mt][nt], ahf[mt][0],ahf[mt][1],ahf[mt][2],ahf[mt][3],
                         blf[nt][0], blf[nt][1]);
                mma16816(acc[mt][nt], alf[mt][0],alf[mt][1],alf[mt][2],alf[mt][3],
                         bhf[nt][0], bhf[nt][1]);
            }
    }

#pragma unroll
    for (int mt = 0; mt < 2; ++mt) {
        int ig = i0 + wm + mt * 16 + orow;
        float* base0 = g_pd + ((size_t)(bh * 1024 + ig)) * 2304;
        float* base1 = base0 + 8 * 2304;
#pragma unroll
        for (int nt = 0; nt < 8; ++nt) {
            int cg = c0 + wn + nt * 8 + rr * 2;
            int j0 = cg - 1023 + ig;
            if (j0 >= 0 && j0 < 2304)         base0[j0]     = acc[mt][nt][0];
            if (j0 + 1 >= 0 && j0 + 1 < 2304) base0[j0 + 1] = acc[mt][nt][1];
            int j1 = j0 + 8;
            if (j1 >= 0 && j1 < 2304)         base1[j1]     = acc[mt][nt][2];
            if (j1 + 1 >= 0 && j1 + 1 < 2304) base1[j1 + 1] = acc[mt][nt][3];
        }
    }
}

// ---------------------------------------------------------------------------
// Flash attention on mma.sync: BQ=128, BK=64, 8 warps x 16 q-rows.
// S = (QK bf16x3 + PD) * 0.125, causal mask kg > qg+1280, online softmax,
// O += P(hi/lo) x V(hi/lo) (x3). Output bf16 hi/lo -> g_ahi/g_alo.
// grid = (qtile 8, h 16, b 4)
// ---------------------------------------------------------------------------
__global__ __launch_bounds__(256, 2)
void attn_mma()
{
    extern __shared__ char smem[];
    const uint32_t s0 = smem_u32(smem);
    const uint32_t QH = s0,          QL = s0 + 18432,
                   KH = s0 + 36864,  KL = s0 + 46080,
                   VH = s0 + 55296,  VL = s0 + 64512;

    const int tid = threadIdx.x, lane = tid & 31, wid = tid >> 5;
    const int qt = blockIdx.x, h = blockIdx.y, b = blockIdx.z;
    const int q0 = qt * 128;
    const int quad = lane >> 3, rin = lane & 7;
    const int orow = lane >> 2, rr = lane & 3;

    // Q tile (persists across k-loop)
#pragma unroll
    for (int i = 0; i < 4; ++i) {
        int idx = tid + i * 256;
        int row = idx >> 3, ch = idx & 7;
        size_t src = ((size_t)(b * 1024 + q0 + row)) * 1024 + h * 64 + ch * 8;
        uint32_t so = (uint32_t)(row * 144 + ch * 16);
        cp16(QH + so, g_qh + src);
        cp16(QL + so, g_ql + src);
    }
    cp_commit();

    float Oacc[8][4];
#pragma unroll
    for (int nt = 0; nt < 8; ++nt)
#pragma unroll
        for (int e = 0; e < 4; ++e) Oacc[nt][e] = 0.f;
    float m0r = -1e30f, m1r = -1e30f, l0r = 0.f, l1r = 0.f;

    const int qg0 = q0 + wid * 16 + orow;
    const float* pdbase = g_pd + ((size_t)((b * 16 + h) * 1024 + qg0)) * 2304;

    const int ntiles = qt * 2 + 22;
    for (int t = 0; t < ntiles; ++t) {
        const int k0 = t * 64;
        __syncthreads();
#pragma unroll
        for (int i = 0; i < 2; ++i) {
            int idx = tid + i * 256;
            int row = idx >> 3, ch = idx & 7;
            size_t srcK = ((size_t)(b * 2304 + k0 + row)) * 2048 + h * 64 + ch * 8;
            uint32_t so = (uint32_t)(row * 144 + ch * 16);
            cp16(KH + so, g_kvh + srcK);
            cp16(KL + so, g_kvl + srcK);
            cp16(VH + so, g_kvh + srcK + 1024);
            cp16(VL + so, g_kvl + srcK + 1024);
        }
        cp_commit();
        asm volatile("cp.async.wait_group 0;" ::: "memory");
        __syncthreads();

        // --- S = Q.K^T (x3) ---
        float sacc[8][4];
#pragma unroll
        for (int nt = 0; nt < 8; ++nt)
#pragma unroll
            for (int e = 0; e < 4; ++e) sacc[nt][e] = 0.f;

#pragma unroll
        for (int ks = 0; ks < 4; ++ks) {
            uint32_t aaddr = (uint32_t)((wid*16 + (quad&1)*8 + rin) * 144
                                        + (ks*16 + (quad>>1)*8) * 2);
            uint32_t ah0, ah1, ah2, ah3, al0, al1, al2, al3;
            ldsm4(ah0, ah1, ah2, ah3, QH + aaddr);
            ldsm4(al0, al1, al2, al3, QL + aaddr);
            uint32_t bh[8][2], bl[8][2];
#pragma unroll
            for (int p = 0; p < 4; ++p) {
                uint32_t baddr = (uint32_t)((p*16 + (quad>>1)*8 + rin) * 144
                                            + (ks*16 + (quad&1)*8) * 2);
                ldsm4(bh[2*p][0], bh[2*p][1], bh[2*p+1][0], bh[2*p+1][1], KH + baddr);
                ldsm4(bl[2*p][0], bl[2*p][1], bl[2*p+1][0], bl[2*p+1][1], KL + baddr);
            }
#pragma unroll
            for (int nt = 0; nt < 8; ++nt) {
                mma16816(sacc[nt], ah0, ah1, ah2, ah3, bh[nt][0], bh[nt][1]);
                mma16816(sacc[nt], ah0, ah1, ah2, ah3, bl[nt][0], bl[nt][1]);
                mma16816(sacc[nt], al0, al1, al2, al3, bh[nt][0], bh[nt][1]);
            }
        }

        // --- + PD, scale, causal mask ---
        const float* pr0 = pdbase + k0;
        const float* pr1 = pr0 + 8 * 2304;
        const int lim0 = qg0 + 1280 - k0;
        const int lim1 = lim0 + 8;
#pragma unroll
        for (int nt = 0; nt < 8; ++nt) {
            int cc = nt * 8 + rr * 2;
            float2 p0 = *(const float2*)(pr0 + cc);
            float2 p1 = *(const float2*)(pr1 + cc);
            sacc[nt][0] = (cc     <= lim0) ? (sacc[nt][0] + p0.x) * 0.125f : -1e30f;
            sacc[nt][1] = (cc + 1 <= lim0) ? (sacc[nt][1] + p0.y) * 0.125f : -1e30f;
            sacc[nt][2] = (cc     <= lim1) ? (sacc[nt][2] + p1.x) * 0.125f : -1e30f;
            sacc[nt][3] = (cc + 1 <= lim1) ? (sacc[nt][3] + p1.y) * 0.125f : -1e30f;
        }

        // --- online softmax (rows orow, orow+8; stats across 4 lanes) ---
        float mx0 = -1e30f, mx1 = -1e30f;
#pragma unroll
        for (int nt = 0; nt < 8; ++nt) {
            mx0 = fmaxf(mx0, fmaxf(sacc[nt][0], sacc[nt][1]));
            mx1 = fmaxf(mx1, fmaxf(sacc[nt][2], sacc[nt][3]));
        }
        mx0 = fmaxf(mx0, __shfl_xor_sync(0xffffffffu, mx0, 1));
        mx0 = fmaxf(mx0, __shfl_xor_sync(0xffffffffu, mx0, 2));
        mx1 = fmaxf(mx1, __shfl_xor_sync(0xffffffffu, mx1, 1));
        mx1 = fmaxf(mx1, __shfl_xor_sync(0xffffffffu, mx1, 2));
        float mn0 = fmaxf(m0r, mx0), mn1 = fmaxf(m1r, mx1);
        float a0 = __expf(m0r - mn0), a1 = __expf(m1r - mn1);
        float su0 = 0.f, su1 = 0.f;
#pragma unroll
        for (int nt = 0; nt < 8; ++nt) {
            float e0 = __expf(sacc[nt][0] - mn0); sacc[nt][0] = e0; su0 += e0;
            float e1 = __expf(sacc[nt][1] - mn0); sacc[nt][1] = e1; su0 += e1;
            float e2 = __expf(sacc[nt][2] - mn1); sacc[nt][2] = e2; su1 += e2;
            float e3 = __expf(sacc[nt][3] - mn1); sacc[nt][3] = e3; su1 += e3;
        }
        su0 += __shfl_xor_sync(0xffffffffu, su0, 1);
        su0 += __shfl_xor_sync(0xffffffffu, su0, 2);
        su1 += __shfl_xor_sync(0xffffffffu, su1, 1);
        su1 += __shfl_xor_sync(0xffffffffu, su1, 2);
        l0r = l0r * a0 + su0; l1r = l1r * a1 + su1;
        m0r = mn0; m1r = mn1;
#pragma unroll
        for (int nt = 0; nt < 8; ++nt) {
            Oacc[nt][0] *= a0; Oacc[nt][1] *= a0;
            Oacc[nt][2] *= a1; Oacc[nt][3] *= a1;
        }

        // --- O += P.V (x3); P frags reused as A operands ---
#pragma unroll
        for (int ks = 0; ks < 4; ++ks) {
            uint32_t pah[4], pal[4];
#pragma unroll
            for (int half = 0; half < 2; ++half) {
                float f0 = sacc[2*ks+half][0], f1 = sacc[2*ks+half][1];
                float f2 = sacc[2*ks+half][2], f3 = sacc[2*ks+half][3];
                __nv_bfloat16 h0 = __float2bfloat16(f0), h1 = __float2bfloat16(f1);
                __nv_bfloat16 h2 = __float2bfloat16(f2), h3 = __float2bfloat16(f3);
                pah[2*half]   = pack2(h0, h1);
                pah[2*half+1] = pack2(h2, h3);
                pal[2*half]   = pack2(__float2bfloat16(f0 - __bfloat162float(h0)),
                                      __float2bfloat16(f1 - __bfloat162float(h1)));
                pal[2*half+1] = pack2(__float2bfloat16(f2 - __bfloat162float(h2)),
                                      __float2bfloat16(f3 - __bfloat162float(h3)));
            }
            uint32_t vh[8][2], vl[8][2];
#pragma unroll
            for (int p = 0; p < 4; ++p) {
                uint32_t vaddr = (uint32_t)((ks*16 + (quad&1)*8 + rin) * 144
                                            + (p*16 + (quad>>1)*8) * 2);
                ldsm4t(vh[2*p][0], vh[2*p][1], vh[2*p+1][0], vh[2*p+1][1], VH + vaddr);
                ldsm4t(vl[2*p][0], vl[2*p][1], vl[2*p+1][0], vl[2*p+1][1], VL + vaddr);
            }
#pragma unroll
            for (int nt = 0; nt < 8; ++nt) {
                mma16816(Oacc[nt], pah[0], pah[1], pah[2], pah[3], vh[nt][0], vh[nt][1]);
                mma16816(Oacc[nt], pah[0], pah[1], pah[2], pah[3], vl[nt][0], vl[nt][1]);
                mma16816(Oacc[nt], pal[0], pal[1], pal[2], pal[3], vh[nt][0], vh[nt][1]);
            }
        }
    }

    // --- epilogue: O/l -> bf16 hi/lo ---
    float i0 = 1.f / l0r, i1 = 1.f / l1r;
    size_t ob = ((size_t)(b * 1024 + qg0)) * 1024 + h * 64;
#pragma unroll
    for (int nt = 0; nt < 8; ++nt) {
        int cc = nt * 8 + rr * 2;
        float f0 = Oacc[nt][0] * i0, f1 = Oacc[nt][1] * i0;
        float f2 = Oacc[nt][2] * i1, f3 = Oacc[nt][3] * i1;
        __nv_bfloat16 h0 = __float2bfloat16(f0), h1 = __float2bfloat16(f1);
        __nv_bfloat16 h2 = __float2bfloat16(f2), h3 = __float2bfloat16(f3);
        *(uint32_t*)&g_ahi[ob + cc] = pack2(h0, h1);
        *(uint32_t*)&g_alo[ob + cc] = pack2(__float2bfloat16(f0 - __bfloat162float(h0)),
                                            __float2bfloat16(f1 - __bfloat162float(h1)));
        *(uint32_t*)&g_ahi[ob + 8*1024 + cc] = pack2(h2, h3);
        *(uint32_t*)&g_alo[ob + 8*1024 + cc] = pack2(__float2bfloat16(f2 - __bfloat162float(h2)),
                                                     __float2bfloat16(f3 - __bfloat162float(h3)));
    }
}

// ---------------------------------------------------------------------------
extern "C" void kernel_launch(void* const* d_in, const int* in_sizes, int n_in,
                              void* d_out, int out_size)
{
    (void)in_sizes; (void)n_in; (void)out_size;
    const float* x     = (const float*)d_in[0];
    const float* memp  = (const float*)d_in[1];
    const float* cmemp = (const float*)d_in[2];
    const float* pos   = (const float*)d_in[3];
    // d_in[4] = input_mask (all True; only causal mask matters)
    const float* Wq    = (const float*)d_in[5];
    const float* Wkv   = (const float*)d_in[6];
    const float* Wout  = (const float*)d_in[7];
    const float* bout  = (const float*)d_in[8];
    const float* convw = (const float*)d_in[9];
    const float* convb = (const float*)d_in[10];
    float* out = (float*)d_out;

    const int GSM = 2 * STG_BYTES;   // 81920
    cudaFuncSetAttribute(gemm_mma<0>, cudaFuncAttributeMaxDynamicSharedMemorySize, GSM);
    cudaFuncSetAttribute(gemm_mma<1>, cudaFuncAttributeMaxDynamicSharedMemorySize, GSM);
    cudaFuncSetAttribute(gemm_mma<2>, cudaFuncAttributeMaxDynamicSharedMemorySize, GSM);
    cudaFuncSetAttribute(gemm_mma<3>, cudaFuncAttributeMaxDynamicSharedMemorySize, GSM);
    cudaFuncSetAttribute(pd_gemm,  cudaFuncAttributeMaxDynamicSharedMemorySize, 73728);
    cudaFuncSetAttribute(attn_mma, cudaFuncAttributeMaxDynamicSharedMemorySize, 73728);

    dim3 blk(256);
    // splits
    split_k<0><<<4096, blk>>>(x,     1048576);
    split_k<1><<<4096, blk>>>(memp,  1048576);
    split_k<2><<<1024, blk>>>(cmemp,  262144);
    split_k<3><<<1024, blk>>>(Wq,     262144);
    split_k<4><<<2048, blk>>>(Wkv,    524288);
    split_k<5><<<1024, blk>>>(Wout,   262144);
    conv_split<<<16384, blk>>>(convw);
    pe_split<<<2304, blk>>>(pos);

    // q = x @ Wq^T -> bf16 hi/lo     (M=4096, N=1024, K=1024)
    gemm_mma<0><<<dim3(8, 32), blk, GSM>>>(nullptr, nullptr, 1024, 1024);
    // PD = shifted(Q . PE^T)
    pd_gemm<<<dim3(18, 8, 64), blk, 73728>>>();
    // kv = [cmem;mem;x] @ Wkv^T -> bf16 hi/lo   (M=9216, N=2048, K=1024)
    gemm_mma<1><<<dim3(16, 72), blk, GSM>>>(nullptr, nullptr, 1024, 2048);
    // attention -> bf16 hi/lo
    attn_mma<<<dim3(8, 16, 4), blk, 73728>>>();
    // logits = ao @ Wout^T + bout -> d_out[0:4M)
    gemm_mma<2><<<dim3(8, 32), blk, GSM>>>(bout, out, 1024, 1024);
    // new_mem = x -> d_out[4M:8M)
    cudaMemcpyAsync(out + 4194304, x, (size_t)4194304 * sizeof(float),
                    cudaMemcpyDeviceToDevice, 0);
    // new_cmem = conv(mem) -> d_out[8M:9M)   (M=1024, N=1024, K=4096)
    gemm_mma<3><<<dim3(8, 8), blk, GSM>>>(convb, out + 8388608, 4096, 1024);
}